// round 1
// baseline (speedup 1.0000x reference)
#include <cuda_runtime.h>
#include <cstdint>

#define NROWS 32768
#define D 256
#define K 4096
#define KH 2048           // K split half
#define DECAY 0.99f
#define ONE_MINUS_DECAY 0.01f
#define EPSV 1e-5f
#define COMMIT 0.25f

// Output layout (float32, concatenated in reference return order)
static const size_t OFF_Q    = 0;                     // 32*1024*256
static const size_t OFF_LOSS = 8388608;
static const size_t OFF_PERP = 8388609;
static const size_t OFF_IDX  = 8388610;               // 32768 (as float)
static const size_t OFF_NE   = 8421378;               // 256*4096

// -------- scratch (device globals; no allocations allowed) --------
__device__ float g_ce[K];                  // ||e_k||^2
__device__ float g_r[NROWS];               // ||x_n||^2
__device__ float g_ET[(size_t)K * D];      // embeddings transposed [K, D]
__device__ float g_dw[(size_t)D * K];      // scatter accumulation
__device__ int   g_counts[K];
__device__ int   g_idx[NROWS];
__device__ float g_minv[NROWS * 2];
__device__ int   g_mini[NROWS * 2];
__device__ float g_loss;
__device__ float g_bias;
__device__ float g_cnorm[K];

// -------- f32x2 helpers (sm_100+ packed fp32 FMA) --------
__device__ __forceinline__ unsigned long long dup2(float a) {
    unsigned long long r;
    asm("mov.b64 %0, {%1, %1};" : "=l"(r) : "f"(a));
    return r;
}
__device__ __forceinline__ void fma2(unsigned long long &acc, unsigned long long a, unsigned long long b) {
    asm("fma.rn.f32x2 %0, %1, %2, %0;" : "+l"(acc) : "l"(a), "l"(b));
}
__device__ __forceinline__ float2 unpack2(unsigned long long v) {
    float2 u;
    asm("mov.b64 {%0, %1}, %2;" : "=f"(u.x), "=f"(u.y) : "l"(v));
    return u;
}

// ============================ small kernels ============================

__global__ void k_zero() {
    int i = blockIdx.x * blockDim.x + threadIdx.x;
    int stride = gridDim.x * blockDim.x;
    for (int j = i; j < D * K; j += stride) g_dw[j] = 0.f;
    for (int j = i; j < K; j += stride) g_counts[j] = 0;
    if (i == 0) g_loss = 0.f;
}

__global__ void k_ce(const float* __restrict__ E) {
    int k = blockIdx.x * 256 + threadIdx.x;
    float s = 0.f;
    #pragma unroll 8
    for (int d = 0; d < D; d++) {
        float v = E[(size_t)d * K + k];
        s = fmaf(v, v, s);
    }
    g_ce[k] = s;
}

__global__ void k_transpose(const float* __restrict__ E) {
    __shared__ float t[32][33];
    int kb = blockIdx.x * 32, db = blockIdx.y * 32;
    int x = threadIdx.x, y0 = threadIdx.y;   // block (32, 8)
    #pragma unroll
    for (int j = 0; j < 32; j += 8)
        t[y0 + j][x] = E[(size_t)(db + y0 + j) * K + kb + x];
    __syncthreads();
    #pragma unroll
    for (int j = 0; j < 32; j += 8)
        g_ET[(size_t)(kb + y0 + j) * D + db + x] = t[x][y0 + j];
}

__global__ void k_rownorm(const float* __restrict__ X) {
    int row = blockIdx.x * 8 + (threadIdx.x >> 5);
    int lane = threadIdx.x & 31;
    const float* xr = X + (size_t)row * D;
    double s = 0.0;
    #pragma unroll
    for (int j = lane; j < D; j += 32) { float v = xr[j]; s += (double)v * (double)v; }
    #pragma unroll
    for (int o = 16; o; o >>= 1) s += __shfl_down_sync(0xffffffffu, s, o);
    if (lane == 0) g_r[row] = (float)s;
}

// ============================ argmin GEMM ============================
// 128 rows x 2048 codes per block (K split in 2).  BK=8, micro-tile 8x8,
// FFMA2 pairs over adjacent codes. 256 threads, 2 CTA/SM.

#define FMAROW(r, av) { unsigned long long ad = dup2(av); \
    fma2(acc[r][0], ad, b0.x); fma2(acc[r][1], ad, b0.y); \
    fma2(acc[r][2], ad, b1.x); fma2(acc[r][3], ad, b1.y); }

__global__ void __launch_bounds__(256, 2)
k_argmin(const float* __restrict__ X, const float* __restrict__ E) {
    const int rt = blockIdx.x >> 1;
    const int h  = blockIdx.x & 1;
    const int row0 = rt * 128;
    const int kbase = h * KH;

    __shared__ __align__(16) float Xs[2][8][128];
    __shared__ __align__(16) float Es[2][8][128];
    __shared__ float rs[128];

    const int tid = threadIdx.x;
    const int tx = tid & 15;     // code group (8 codes)
    const int ty = tid >> 4;     // row group (8 rows)

    if (tid < 128) rs[tid] = g_r[row0 + tid];

    const int xrow = tid >> 1, xh = (tid & 1) * 4;
    const int edd = tid >> 5, ekk = (tid & 31) * 4;

    unsigned long long acc[8][4];
    float minv[8]; int mini[8];
    #pragma unroll
    for (int r = 0; r < 8; r++) {
        minv[r] = 3.4e38f; mini[r] = 0x7fffffff;
        #pragma unroll
        for (int c = 0; c < 4; c++) acc[r][c] = 0ULL;
    }

    // prologue: load step 0 (ktile 0, d0 = 0)
    {
        float4 xv = *(const float4*)&X[(size_t)(row0 + xrow) * D + xh];
        float4 ev = *(const float4*)&E[(size_t)edd * K + kbase + ekk];
        Xs[0][xh + 0][xrow] = xv.x; Xs[0][xh + 1][xrow] = xv.y;
        Xs[0][xh + 2][xrow] = xv.z; Xs[0][xh + 3][xrow] = xv.w;
        *(float4*)&Es[0][edd][ekk] = ev;
    }
    __syncthreads();

    int cur = 0;
    const int NSTEPS = (KH / 128) * (D / 8);   // 16 * 32 = 512
    #pragma unroll 1
    for (int step = 0; step < NSTEPS; step++) {
        const int nstep = step + 1;
        const bool more = (nstep < NSTEPS);
        float4 nx, ne;
        if (more) {
            int nkt = nstep >> 5;
            int nd0 = (nstep & 31) * 8;
            nx = *(const float4*)&X[(size_t)(row0 + xrow) * D + nd0 + xh];
            ne = *(const float4*)&E[(size_t)(nd0 + edd) * K + kbase + nkt * 128 + ekk];
        }

        // compute 8 dd from buffer cur
        #pragma unroll
        for (int dd = 0; dd < 8; dd++) {
            float4 a0 = *(const float4*)&Xs[cur][dd][ty * 8];
            float4 a1 = *(const float4*)&Xs[cur][dd][ty * 8 + 4];
            ulonglong2 b0 = *(const ulonglong2*)&Es[cur][dd][tx * 8];
            ulonglong2 b1 = *(const ulonglong2*)&Es[cur][dd][tx * 8 + 4];
            FMAROW(0, a0.x) FMAROW(1, a0.y) FMAROW(2, a0.z) FMAROW(3, a0.w)
            FMAROW(4, a1.x) FMAROW(5, a1.y) FMAROW(6, a1.z) FMAROW(7, a1.w)
        }

        // end of a 128-code tile: distances + running argmin, reset acc
        if ((step & 31) == 31) {
            const int kt = step >> 5;
            const int kcol0 = kbase + kt * 128 + tx * 8;
            float4 c0 = *(const float4*)&g_ce[kcol0];
            float4 c1 = *(const float4*)&g_ce[kcol0 + 4];
            float cv[8] = {c0.x, c0.y, c0.z, c0.w, c1.x, c1.y, c1.z, c1.w};
            #pragma unroll
            for (int r = 0; r < 8; r++) {
                float rr = rs[ty * 8 + r];
                #pragma unroll
                for (int cp = 0; cp < 4; cp++) {
                    float2 mm = unpack2(acc[r][cp]);
                    float dv0 = (rr - 2.0f * mm.x) + cv[2 * cp];
                    float dv1 = (rr - 2.0f * mm.y) + cv[2 * cp + 1];
                    if (dv0 < minv[r]) { minv[r] = dv0; mini[r] = kcol0 + 2 * cp; }
                    if (dv1 < minv[r]) { minv[r] = dv1; mini[r] = kcol0 + 2 * cp + 1; }
                    acc[r][cp] = 0ULL;
                }
            }
        }

        if (more) {
            const int nb = cur ^ 1;
            Xs[nb][xh + 0][xrow] = nx.x; Xs[nb][xh + 1][xrow] = nx.y;
            Xs[nb][xh + 2][xrow] = nx.z; Xs[nb][xh + 3][xrow] = nx.w;
            *(float4*)&Es[nb][edd][ekk] = ne;
            __syncthreads();
            cur = nb;
        }
    }

    // cross-thread reduction: 16 threads per row, first-min tie rule (smaller k)
    __syncthreads();
    float* red_v = &Xs[0][0][0];           // 2048 floats — exactly fits
    int*   red_i = (int*)&Es[0][0][0];
    #pragma unroll
    for (int r = 0; r < 8; r++) {
        int row = ty * 8 + r;
        red_v[row * 16 + tx] = minv[r];
        red_i[row * 16 + tx] = mini[r];
    }
    __syncthreads();
    if (tid < 128) {
        float bv = red_v[tid * 16]; int bi = red_i[tid * 16];
        #pragma unroll
        for (int j = 1; j < 16; j++) {
            float v = red_v[tid * 16 + j]; int ii = red_i[tid * 16 + j];
            if (v < bv || (v == bv && ii < bi)) { bv = v; bi = ii; }
        }
        g_minv[(size_t)(row0 + tid) * 2 + h] = bv;
        g_mini[(size_t)(row0 + tid) * 2 + h] = bi;
    }
}

__global__ void k_merge(float* __restrict__ out_idx) {
    int n = blockIdx.x * blockDim.x + threadIdx.x;
    if (n >= NROWS) return;
    float v0 = g_minv[n * 2], v1 = g_minv[n * 2 + 1];
    int i0 = g_mini[n * 2], i1 = g_mini[n * 2 + 1];
    int sel = (v1 < v0 || (v1 == v0 && i1 < i0)) ? i1 : i0;
    g_idx[n] = sel;
    out_idx[n] = (float)sel;
}

// gather quantized + loss partial + dw scatter + counts
__global__ void k_scatter(const float* __restrict__ X, float* __restrict__ out_q) {
    int row = blockIdx.x * 8 + (threadIdx.x >> 5);
    int lane = threadIdx.x & 31;
    int k = g_idx[row];
    const float4* et = (const float4*)(g_ET + (size_t)k * D);
    const float4* xr = (const float4*)(X + (size_t)row * D);
    float4* qo = (float4*)(out_q + (size_t)row * D);
    float ls = 0.f;
    #pragma unroll
    for (int it = 0; it < 2; it++) {
        int v = it * 32 + lane;       // float4 index within row, 0..63
        float4 q = et[v];
        float4 xv = xr[v];
        qo[v] = q;
        float dx = q.x - xv.x, dy = q.y - xv.y, dz = q.z - xv.z, dw = q.w - xv.w;
        ls += dx * dx + dy * dy + dz * dz + dw * dw;
        int d = v * 4;
        atomicAdd(&g_dw[(size_t)(d + 0) * K + k], xv.x);
        atomicAdd(&g_dw[(size_t)(d + 1) * K + k], xv.y);
        atomicAdd(&g_dw[(size_t)(d + 2) * K + k], xv.z);
        atomicAdd(&g_dw[(size_t)(d + 3) * K + k], xv.w);
    }
    #pragma unroll
    for (int o = 16; o; o >>= 1) ls += __shfl_down_sync(0xffffffffu, ls, o);
    if (lane == 0) {
        atomicAdd(&g_loss, ls);
        atomicAdd(&g_counts[k], 1);
    }
}

// cluster stats, scalars, cluster_norm
__global__ void k_stats(const float* __restrict__ ema_counter,
                        const float* __restrict__ ema_cluster,
                        float* __restrict__ out) {
    __shared__ float sh[64];
    __shared__ float sh_n;
    int tid = threadIdx.x;
    float counter = ema_counter[0] + 1.0f;
    float bias = 1.0f - powf(DECAY, counter);
    float cavg[4]; float npart = 0.f, epart = 0.f;
    #pragma unroll
    for (int j = 0; j < 4; j++) {
        int k = tid + j * 1024;
        float cnt = (float)g_counts[k];
        float ch = ema_cluster[k] * DECAY + cnt * ONE_MINUS_DECAY;
        float ca = ch / bias;
        cavg[j] = ca; npart += ca;
        float p = cnt * (1.0f / (float)NROWS);
        epart += p * logf(p + 1e-10f);
    }
    #pragma unroll
    for (int o = 16; o; o >>= 1) {
        npart += __shfl_down_sync(0xffffffffu, npart, o);
        epart += __shfl_down_sync(0xffffffffu, epart, o);
    }
    if ((tid & 31) == 0) { sh[tid >> 5] = npart; sh[32 + (tid >> 5)] = epart; }
    __syncthreads();
    if (tid < 32) {
        float a = sh[tid], b = sh[32 + tid];
        #pragma unroll
        for (int o = 16; o; o >>= 1) {
            a += __shfl_down_sync(0xffffffffu, a, o);
            b += __shfl_down_sync(0xffffffffu, b, o);
        }
        if (tid == 0) {
            sh_n = a;
            out[OFF_PERP] = expf(-b);
            float el = g_loss / (float)((size_t)NROWS * D);
            out[OFF_LOSS] = el + COMMIT * el;
            g_bias = bias;
        }
    }
    __syncthreads();
    float n = sh_n;
    #pragma unroll
    for (int j = 0; j < 4; j++) {
        int k = tid + j * 1024;
        g_cnorm[k] = (cavg[j] + EPSV) / (n + (float)K * EPSV) * n;
    }
}

__global__ void k_newemb(const float* __restrict__ ema_dw, float* __restrict__ out_ne) {
    int i = blockIdx.x * 256 + threadIdx.x;   // i = d*K + k
    int k = i & (K - 1);
    float dwh = ema_dw[i] * DECAY + g_dw[i] * ONE_MINUS_DECAY;
    out_ne[i] = (dwh / g_bias) / g_cnorm[k];
}

// ============================ launch ============================

extern "C" void kernel_launch(void* const* d_in, const int* in_sizes, int n_in,
                              void* d_out, int out_size) {
    const float* x   = (const float*)d_in[0];
    const float* emb = (const float*)d_in[1];
    const float* ctr = (const float*)d_in[2];
    const float* ecl = (const float*)d_in[3];
    const float* edw = (const float*)d_in[4];
    float* out = (float*)d_out;

    k_zero<<<1024, 256>>>();
    k_ce<<<K / 256, 256>>>(emb);
    k_transpose<<<dim3(K / 32, D / 32), dim3(32, 8)>>>(emb);
    k_rownorm<<<NROWS / 8, 256>>>(x);
    k_argmin<<<512, 256>>>(x, emb);
    k_merge<<<NROWS / 256, 256>>>(out + OFF_IDX);
    k_scatter<<<NROWS / 8, 256>>>(x, out + OFF_Q);
    k_stats<<<1, 1024>>>(ctr, ecl, out);
    k_newemb<<<(D * K) / 256, 256>>>(edw, out + OFF_NE);
}

// round 2
// speedup vs baseline: 1.0011x; 1.0011x over previous
#include <cuda_runtime.h>
#include <cstdint>

#define NROWS 32768
#define D 256
#define K 4096
#define KH 2048           // K split half
#define DECAY 0.99f
#define ONE_MINUS_DECAY 0.01f
#define EPSV 1e-5f
#define COMMIT 0.25f

// Output layout (float32, concatenated in reference return order)
static const size_t OFF_Q    = 0;                     // 32*1024*256
static const size_t OFF_LOSS = 8388608;
static const size_t OFF_PERP = 8388609;
static const size_t OFF_IDX  = 8388610;               // 32768 (as float)
static const size_t OFF_NE   = 8421378;               // 256*4096

// -------- scratch (device globals; no allocations allowed) --------
__device__ float g_ce[K];                  // ||e_k||^2
__device__ float g_r[NROWS];               // ||x_n||^2
__device__ float g_ET[(size_t)K * D];      // embeddings transposed [K, D]
__device__ float g_dw[(size_t)D * K];      // scatter accumulation
__device__ int   g_counts[K];
__device__ int   g_idx[NROWS];
__device__ float g_minv[NROWS * 2];
__device__ int   g_mini[NROWS * 2];
__device__ float g_loss;
__device__ float g_bias;
__device__ float g_cnorm[K];

// -------- f32x2 helpers (sm_100+ packed fp32 FMA) --------
__device__ __forceinline__ unsigned long long dup2(float a) {
    unsigned long long r;
    asm("mov.b64 %0, {%1, %1};" : "=l"(r) : "f"(a));
    return r;
}
__device__ __forceinline__ void fma2(unsigned long long &acc, unsigned long long a, unsigned long long b) {
    asm("fma.rn.f32x2 %0, %1, %2, %0;" : "+l"(acc) : "l"(a), "l"(b));
}
__device__ __forceinline__ float2 unpack2(unsigned long long v) {
    float2 u;
    asm("mov.b64 {%0, %1}, %2;" : "=f"(u.x), "=f"(u.y) : "l"(v));
    return u;
}

// ============================ small kernels ============================

__global__ void k_zero() {
    int i = blockIdx.x * blockDim.x + threadIdx.x;
    int stride = gridDim.x * blockDim.x;
    for (int j = i; j < D * K; j += stride) g_dw[j] = 0.f;
    for (int j = i; j < K; j += stride) g_counts[j] = 0;
    if (i == 0) g_loss = 0.f;
}

__global__ void k_ce(const float* __restrict__ E) {
    int k = blockIdx.x * 256 + threadIdx.x;
    float s = 0.f;
    #pragma unroll 8
    for (int d = 0; d < D; d++) {
        float v = E[(size_t)d * K + k];
        s = fmaf(v, v, s);
    }
    g_ce[k] = s;
}

__global__ void k_transpose(const float* __restrict__ E) {
    __shared__ float t[32][33];
    int kb = blockIdx.x * 32, db = blockIdx.y * 32;
    int x = threadIdx.x, y0 = threadIdx.y;   // block (32, 8)
    #pragma unroll
    for (int j = 0; j < 32; j += 8)
        t[y0 + j][x] = E[(size_t)(db + y0 + j) * K + kb + x];
    __syncthreads();
    #pragma unroll
    for (int j = 0; j < 32; j += 8)
        g_ET[(size_t)(kb + y0 + j) * D + db + x] = t[x][y0 + j];
}

__global__ void k_rownorm(const float* __restrict__ X) {
    int row = blockIdx.x * 8 + (threadIdx.x >> 5);
    int lane = threadIdx.x & 31;
    const float* xr = X + (size_t)row * D;
    double s = 0.0;
    #pragma unroll
    for (int j = lane; j < D; j += 32) { float v = xr[j]; s += (double)v * (double)v; }
    #pragma unroll
    for (int o = 16; o; o >>= 1) s += __shfl_down_sync(0xffffffffu, s, o);
    if (lane == 0) g_r[row] = (float)s;
}

// ============================ argmin GEMM ============================
// 128 rows x 2048 codes per block (K split in 2).  BK=8, micro-tile 8x8,
// FFMA2 pairs over adjacent codes. 256 threads, 2 CTA/SM.

#define FMAROW(r, av) { unsigned long long ad = dup2(av); \
    fma2(acc[r][0], ad, b0.x); fma2(acc[r][1], ad, b0.y); \
    fma2(acc[r][2], ad, b1.x); fma2(acc[r][3], ad, b1.y); }

__global__ void __launch_bounds__(256, 2)
k_argmin(const float* __restrict__ X, const float* __restrict__ E) {
    const int rt = blockIdx.x >> 1;
    const int h  = blockIdx.x & 1;
    const int row0 = rt * 128;
    const int kbase = h * KH;

    __shared__ __align__(16) float Xs[2][8][128];
    __shared__ __align__(16) float Es[2][8][128];
    __shared__ float rs[128];

    const int tid = threadIdx.x;
    const int tx = tid & 15;     // code group (8 codes)
    const int ty = tid >> 4;     // row group (8 rows)

    if (tid < 128) rs[tid] = g_r[row0 + tid];

    const int xrow = tid >> 1, xh = (tid & 1) * 4;
    const int edd = tid >> 5, ekk = (tid & 31) * 4;

    unsigned long long acc[8][4];
    float minv[8]; int mini[8];
    #pragma unroll
    for (int r = 0; r < 8; r++) {
        minv[r] = 3.4e38f; mini[r] = 0x7fffffff;
        #pragma unroll
        for (int c = 0; c < 4; c++) acc[r][c] = 0ULL;
    }

    // prologue: load step 0 (ktile 0, d0 = 0)
    {
        float4 xv = *(const float4*)&X[(size_t)(row0 + xrow) * D + xh];
        float4 ev = *(const float4*)&E[(size_t)edd * K + kbase + ekk];
        Xs[0][xh + 0][xrow] = xv.x; Xs[0][xh + 1][xrow] = xv.y;
        Xs[0][xh + 2][xrow] = xv.z; Xs[0][xh + 3][xrow] = xv.w;
        *(float4*)&Es[0][edd][ekk] = ev;
    }
    __syncthreads();

    int cur = 0;
    const int NSTEPS = (KH / 128) * (D / 8);   // 16 * 32 = 512
    #pragma unroll 1
    for (int step = 0; step < NSTEPS; step++) {
        const int nstep = step + 1;
        const bool more = (nstep < NSTEPS);
        float4 nx, ne;
        if (more) {
            int nkt = nstep >> 5;
            int nd0 = (nstep & 31) * 8;
            nx = *(const float4*)&X[(size_t)(row0 + xrow) * D + nd0 + xh];
            ne = *(const float4*)&E[(size_t)(nd0 + edd) * K + kbase + nkt * 128 + ekk];
        }

        // compute 8 dd from buffer cur
        #pragma unroll
        for (int dd = 0; dd < 8; dd++) {
            float4 a0 = *(const float4*)&Xs[cur][dd][ty * 8];
            float4 a1 = *(const float4*)&Xs[cur][dd][ty * 8 + 4];
            ulonglong2 b0 = *(const ulonglong2*)&Es[cur][dd][tx * 8];
            ulonglong2 b1 = *(const ulonglong2*)&Es[cur][dd][tx * 8 + 4];
            FMAROW(0, a0.x) FMAROW(1, a0.y) FMAROW(2, a0.z) FMAROW(3, a0.w)
            FMAROW(4, a1.x) FMAROW(5, a1.y) FMAROW(6, a1.z) FMAROW(7, a1.w)
        }

        // end of a 128-code tile: distances + running argmin, reset acc
        if ((step & 31) == 31) {
            const int kt = step >> 5;
            const int kcol0 = kbase + kt * 128 + tx * 8;
            float4 c0 = *(const float4*)&g_ce[kcol0];
            float4 c1 = *(const float4*)&g_ce[kcol0 + 4];
            float cv[8] = {c0.x, c0.y, c0.z, c0.w, c1.x, c1.y, c1.z, c1.w};
            #pragma unroll
            for (int r = 0; r < 8; r++) {
                float rr = rs[ty * 8 + r];
                #pragma unroll
                for (int cp = 0; cp < 4; cp++) {
                    float2 mm = unpack2(acc[r][cp]);
                    float dv0 = (rr - 2.0f * mm.x) + cv[2 * cp];
                    float dv1 = (rr - 2.0f * mm.y) + cv[2 * cp + 1];
                    if (dv0 < minv[r]) { minv[r] = dv0; mini[r] = kcol0 + 2 * cp; }
                    if (dv1 < minv[r]) { minv[r] = dv1; mini[r] = kcol0 + 2 * cp + 1; }
                    acc[r][cp] = 0ULL;
                }
            }
        }

        if (more) {
            const int nb = cur ^ 1;
            Xs[nb][xh + 0][xrow] = nx.x; Xs[nb][xh + 1][xrow] = nx.y;
            Xs[nb][xh + 2][xrow] = nx.z; Xs[nb][xh + 3][xrow] = nx.w;
            *(float4*)&Es[nb][edd][ekk] = ne;
            __syncthreads();
            cur = nb;
        }
    }

    // cross-thread reduction: 16 threads per row, first-min tie rule (smaller k)
    __syncthreads();
    float* red_v = &Xs[0][0][0];           // 2048 floats — exactly fits
    int*   red_i = (int*)&Es[0][0][0];
    #pragma unroll
    for (int r = 0; r < 8; r++) {
        int row = ty * 8 + r;
        red_v[row * 16 + tx] = minv[r];
        red_i[row * 16 + tx] = mini[r];
    }
    __syncthreads();
    if (tid < 128) {
        float bv = red_v[tid * 16]; int bi = red_i[tid * 16];
        #pragma unroll
        for (int j = 1; j < 16; j++) {
            float v = red_v[tid * 16 + j]; int ii = red_i[tid * 16 + j];
            if (v < bv || (v == bv && ii < bi)) { bv = v; bi = ii; }
        }
        g_minv[(size_t)(row0 + tid) * 2 + h] = bv;
        g_mini[(size_t)(row0 + tid) * 2 + h] = bi;
    }
}

__global__ void k_merge(float* __restrict__ out_idx) {
    int n = blockIdx.x * blockDim.x + threadIdx.x;
    if (n >= NROWS) return;
    float v0 = g_minv[n * 2], v1 = g_minv[n * 2 + 1];
    int i0 = g_mini[n * 2], i1 = g_mini[n * 2 + 1];
    int sel = (v1 < v0 || (v1 == v0 && i1 < i0)) ? i1 : i0;
    g_idx[n] = sel;
    out_idx[n] = (float)sel;
}

// gather quantized + loss partial + dw scatter + counts
__global__ void k_scatter(const float* __restrict__ X, float* __restrict__ out_q) {
    int row = blockIdx.x * 8 + (threadIdx.x >> 5);
    int lane = threadIdx.x & 31;
    int k = g_idx[row];
    const float4* et = (const float4*)(g_ET + (size_t)k * D);
    const float4* xr = (const float4*)(X + (size_t)row * D);
    float4* qo = (float4*)(out_q + (size_t)row * D);
    float ls = 0.f;
    #pragma unroll
    for (int it = 0; it < 2; it++) {
        int v = it * 32 + lane;       // float4 index within row, 0..63
        float4 q = et[v];
        float4 xv = xr[v];
        qo[v] = q;
        float dx = q.x - xv.x, dy = q.y - xv.y, dz = q.z - xv.z, dw = q.w - xv.w;
        ls += dx * dx + dy * dy + dz * dz + dw * dw;
        int d = v * 4;
        atomicAdd(&g_dw[(size_t)(d + 0) * K + k], xv.x);
        atomicAdd(&g_dw[(size_t)(d + 1) * K + k], xv.y);
        atomicAdd(&g_dw[(size_t)(d + 2) * K + k], xv.z);
        atomicAdd(&g_dw[(size_t)(d + 3) * K + k], xv.w);
    }
    #pragma unroll
    for (int o = 16; o; o >>= 1) ls += __shfl_down_sync(0xffffffffu, ls, o);
    if (lane == 0) {
        atomicAdd(&g_loss, ls);
        atomicAdd(&g_counts[k], 1);
    }
}

// cluster stats, scalars, cluster_norm
__global__ void k_stats(const float* __restrict__ ema_counter,
                        const float* __restrict__ ema_cluster,
                        float* __restrict__ out) {
    __shared__ float sh[64];
    __shared__ float sh_n;
    int tid = threadIdx.x;
    float counter = ema_counter[0] + 1.0f;
    float bias = 1.0f - powf(DECAY, counter);
    float cavg[4]; float npart = 0.f, epart = 0.f;
    #pragma unroll
    for (int j = 0; j < 4; j++) {
        int k = tid + j * 1024;
        float cnt = (float)g_counts[k];
        float ch = ema_cluster[k] * DECAY + cnt * ONE_MINUS_DECAY;
        float ca = ch / bias;
        cavg[j] = ca; npart += ca;
        float p = cnt * (1.0f / (float)NROWS);
        epart += p * logf(p + 1e-10f);
    }
    #pragma unroll
    for (int o = 16; o; o >>= 1) {
        npart += __shfl_down_sync(0xffffffffu, npart, o);
        epart += __shfl_down_sync(0xffffffffu, epart, o);
    }
    if ((tid & 31) == 0) { sh[tid >> 5] = npart; sh[32 + (tid >> 5)] = epart; }
    __syncthreads();
    if (tid < 32) {
        float a = sh[tid], b = sh[32 + tid];
        #pragma unroll
        for (int o = 16; o; o >>= 1) {
            a += __shfl_down_sync(0xffffffffu, a, o);
            b += __shfl_down_sync(0xffffffffu, b, o);
        }
        if (tid == 0) {
            sh_n = a;
            out[OFF_PERP] = expf(-b);
            float el = g_loss / (float)((size_t)NROWS * D);
            out[OFF_LOSS] = el + COMMIT * el;
            g_bias = bias;
        }
    }
    __syncthreads();
    float n = sh_n;
    #pragma unroll
    for (int j = 0; j < 4; j++) {
        int k = tid + j * 1024;
        g_cnorm[k] = (cavg[j] + EPSV) / (n + (float)K * EPSV) * n;
    }
}

__global__ void k_newemb(const float* __restrict__ ema_dw, float* __restrict__ out_ne) {
    int i = blockIdx.x * 256 + threadIdx.x;   // i = d*K + k
    int k = i & (K - 1);
    float dwh = ema_dw[i] * DECAY + g_dw[i] * ONE_MINUS_DECAY;
    out_ne[i] = (dwh / g_bias) / g_cnorm[k];
}

// ============================ launch ============================

extern "C" void kernel_launch(void* const* d_in, const int* in_sizes, int n_in,
                              void* d_out, int out_size) {
    const float* x   = (const float*)d_in[0];
    const float* emb = (const float*)d_in[1];
    const float* ctr = (const float*)d_in[2];
    const float* ecl = (const float*)d_in[3];
    const float* edw = (const float*)d_in[4];
    float* out = (float*)d_out;

    k_zero<<<1024, 256>>>();
    k_ce<<<K / 256, 256>>>(emb);
    k_transpose<<<dim3(K / 32, D / 32), dim3(32, 8)>>>(emb);
    k_rownorm<<<NROWS / 8, 256>>>(x);
    k_argmin<<<512, 256>>>(x, emb);
    k_merge<<<NROWS / 256, 256>>>(out + OFF_IDX);
    k_scatter<<<NROWS / 8, 256>>>(x, out + OFF_Q);
    k_stats<<<1, 1024>>>(ctr, ecl, out);
    k_newemb<<<(D * K) / 256, 256>>>(edw, out + OFF_NE);
}

// round 4
// speedup vs baseline: 2.8789x; 2.8756x over previous
#include <cuda_runtime.h>
#include <cuda_fp16.h>
#include <cstdint>

#define NROWS 32768
#define D 256
#define K 4096
#define KTOT 768
#define DECAY 0.99f
#define ONE_MINUS_DECAY 0.01f
#define EPSV 1e-5f
#define COMMIT 0.25f

static const size_t OFF_Q    = 0;
static const size_t OFF_LOSS = 8388608;
static const size_t OFF_PERP = 8388609;
static const size_t OFF_IDX  = 8388610;
static const size_t OFF_NE   = 8421378;

// -------- device scratch --------
__device__ float g_ce[K];
__device__ float g_ET[(size_t)K * D];
__device__ __align__(16) __half g_xh[(size_t)NROWS * KTOT];   // [row][x0 | x0/64 | 64*x1]
__device__ __align__(16) __half g_eh[(size_t)K * KTOT];       // [code][e0 | 64*e1 | e0/64]
__device__ float g_dw[(size_t)D * K];
__device__ int   g_counts[K];
__device__ int   g_idx[NROWS];
__device__ float g_minv[(size_t)NROWS * 32];
__device__ int   g_mini[(size_t)NROWS * 32];
__device__ float g_loss;
__device__ float g_bias;
__device__ float g_cnorm[K];

// ================= PTX helpers (base ISA only) =================
__device__ __forceinline__ uint32_t smem_to_u32(const void* p) {
    uint32_t a;
    asm("{ .reg .u64 t; cvta.to.shared.u64 t, %1; cvt.u32.u64 %0, t; }" : "=r"(a) : "l"(p));
    return a;
}
__device__ __forceinline__ void cp16(uint32_t saddr, const void* g) {
    asm volatile("cp.async.cg.shared.global [%0], [%1], 16;" :: "r"(saddr), "l"(g));
}
#define CP_COMMIT() asm volatile("cp.async.commit_group;" ::: "memory")
#define CP_WAIT2()  asm volatile("cp.async.wait_group 2;" ::: "memory")

#define LDSM4(r0, r1, r2, r3, a) \
    asm volatile("ldmatrix.sync.aligned.m8n8.x4.shared.b16 {%0,%1,%2,%3}, [%4];" \
        : "=r"(r0), "=r"(r1), "=r"(r2), "=r"(r3) : "r"(a))
#define LDSM2(r0, r1, a) \
    asm volatile("ldmatrix.sync.aligned.m8n8.x2.shared.b16 {%0,%1}, [%2];" \
        : "=r"(r0), "=r"(r1) : "r"(a))

__device__ __forceinline__ void mma16816(float* c, const uint32_t* a, const uint32_t* b) {
    asm volatile("mma.sync.aligned.m16n8k16.row.col.f32.f16.f16.f32 "
        "{%0,%1,%2,%3}, {%4,%5,%6,%7}, {%8,%9}, {%0,%1,%2,%3};"
        : "+f"(c[0]), "+f"(c[1]), "+f"(c[2]), "+f"(c[3])
        : "r"(a[0]), "r"(a[1]), "r"(a[2]), "r"(a[3]), "r"(b[0]), "r"(b[1]));
}

__device__ __forceinline__ uint32_t sw128(uint32_t b) { return b ^ ((b >> 3) & 0x70); }

// ================= split helpers =================
__device__ __forceinline__ void xsplit1(float x, __half& s0, __half& s1, __half& s2) {
    s0 = __float2half_rn(x);
    float x0 = __half2float(s0);
    s1 = __float2half_rn(x0 * 0.015625f);          // x0/64
    s2 = __float2half_rn((x - x0) * 64.0f);        // 64*x1
}
__device__ __forceinline__ void esplit1(float e, __half& s0, __half& s1, __half& s2) {
    s0 = __float2half_rn(e);
    float e0 = __half2float(s0);
    s1 = __float2half_rn((e - e0) * 64.0f);        // 64*e1
    s2 = __float2half_rn(e0 * 0.015625f);          // e0/64
}

// ================= small kernels =================
__global__ void k_zero() {
    int i = blockIdx.x * blockDim.x + threadIdx.x, st = gridDim.x * blockDim.x;
    for (int j = i; j < D * K; j += st) g_dw[j] = 0.f;
    for (int j = i; j < K; j += st) g_counts[j] = 0;
    if (i == 0) g_loss = 0.f;
}

__global__ void k_ce(const float* __restrict__ E) {
    int k = blockIdx.x * 256 + threadIdx.x;
    float s = 0.f;
    #pragma unroll 8
    for (int d = 0; d < D; d++) { float v = E[(size_t)d * K + k]; s = fmaf(v, v, s); }
    g_ce[k] = s;
}

__global__ void k_transpose(const float* __restrict__ E) {
    __shared__ float t[32][33];
    int kb = blockIdx.x * 32, db = blockIdx.y * 32;
    int x = threadIdx.x, y0 = threadIdx.y;
    #pragma unroll
    for (int j = 0; j < 32; j += 8) t[y0 + j][x] = E[(size_t)(db + y0 + j) * K + kb + x];
    __syncthreads();
    #pragma unroll
    for (int j = 0; j < 32; j += 8) g_ET[(size_t)(kb + y0 + j) * D + db + x] = t[x][y0 + j];
}

__global__ void k_xsplit(const float* __restrict__ X) {
    size_t i = (size_t)blockIdx.x * 256 + threadIdx.x;  // float4 idx
    float4 v = *(const float4*)(X + i * 4);
    size_t row = i >> 6;
    int c = (int)(i & 63) * 4;
    __half a0[4], a1[4], a2[4];
    xsplit1(v.x, a0[0], a1[0], a2[0]);
    xsplit1(v.y, a0[1], a1[1], a2[1]);
    xsplit1(v.z, a0[2], a1[2], a2[2]);
    xsplit1(v.w, a0[3], a1[3], a2[3]);
    __half* base = g_xh + row * KTOT + c;
    *(uint2*)(base)       = *(uint2*)a0;
    *(uint2*)(base + 256) = *(uint2*)a1;
    *(uint2*)(base + 512) = *(uint2*)a2;
}

__global__ void k_esplit() {
    size_t i = (size_t)blockIdx.x * 256 + threadIdx.x;  // float4 idx of g_ET
    float4 v = *(const float4*)(g_ET + i * 4);
    size_t row = i >> 6;
    int c = (int)(i & 63) * 4;
    __half a0[4], a1[4], a2[4];
    esplit1(v.x, a0[0], a1[0], a2[0]);
    esplit1(v.y, a0[1], a1[1], a2[1]);
    esplit1(v.z, a0[2], a1[2], a2[2]);
    esplit1(v.w, a0[3], a1[3], a2[3]);
    __half* base = g_eh + row * KTOT + c;
    *(uint2*)(base)       = *(uint2*)a0;
    *(uint2*)(base + 256) = *(uint2*)a1;
    *(uint2*)(base + 512) = *(uint2*)a2;
}

// ================= argmin GEMM (HMMA) =================
// grid = 8192: rt = bid>>5 (128 rows), cg = bid&31 (128 codes)
// smem: 3 stages x (A 16KB + B 16KB) = 96KB, cs 512B, red 4KB
#define ST_SZ   32768
#define SM_CS   98304
#define SM_RV   98816
#define SM_RI   100864
#define SMEM_SZ 102912

__global__ void __launch_bounds__(256, 2)
k_argmin() {
    extern __shared__ char smem[];
    const int tid = threadIdx.x;
    const int wid = tid >> 5, lane = tid & 31;
    const int rt = blockIdx.x >> 5, cg = blockIdx.x & 31;
    const int row0 = rt * 128, kc0 = cg * 128;
    const int wr = wid >> 2, wc = wid & 3;
    const uint32_t sb = smem_to_u32(smem);

    float* cs = (float*)(smem + SM_CS);
    if (tid < 128) cs[tid] = g_ce[kc0 + tid];

    const __half* Ag = g_xh + (size_t)row0 * KTOT;
    const __half* Bg = g_eh + (size_t)kc0 * KTOT;

    float acc[4][4][4];
    #pragma unroll
    for (int mt = 0; mt < 4; mt++)
        #pragma unroll
        for (int nt = 0; nt < 4; nt++)
            #pragma unroll
            for (int j = 0; j < 4; j++) acc[mt][nt][j] = 0.f;

    const int r_ = tid >> 1;                 // not used; placeholder removed
    (void)r_;

    // stage loader: stage st -> buffer st%3
    auto issue = [&](int st) {
        int buf = st - (st / 3) * 3;
        uint32_t abase = sb + (uint32_t)buf * ST_SZ;
        uint32_t bbase = abase + 16384;
        int k0 = st * 64;
        #pragma unroll
        for (int j = 0; j < 4; j++) {
            int chunk = tid + j * 256;
            int r = chunk >> 3, cc = chunk & 7;
            uint32_t so = sw128((uint32_t)(r * 128 + cc * 16));
            const __half* ga = Ag + (size_t)r * KTOT + k0 + cc * 8;
            const __half* gb = Bg + (size_t)r * KTOT + k0 + cc * 8;
            cp16(abase + so, ga);
            cp16(bbase + so, gb);
        }
        CP_COMMIT();
    };

    issue(0); issue(1); issue(2);

    const int l15 = lane & 15;

    #pragma unroll 1
    for (int st = 0; st < 12; st++) {
        CP_WAIT2();
        __syncthreads();
        int buf = st - (st / 3) * 3;
        uint32_t abase = sb + (uint32_t)buf * ST_SZ;
        uint32_t bbase = abase + 16384;

        #pragma unroll
        for (int s = 0; s < 4; s++) {
            uint32_t af[4][4], bf[4][2];
            #pragma unroll
            for (int mt = 0; mt < 4; mt++) {
                uint32_t ro = sw128((uint32_t)((wr * 64 + mt * 16 + l15) * 128 + s * 32 + (lane >> 4) * 16));
                LDSM4(af[mt][0], af[mt][1], af[mt][2], af[mt][3], abase + ro);
            }
            #pragma unroll
            for (int nt = 0; nt < 4; nt++) {
                uint32_t ro = sw128((uint32_t)((wc * 32 + nt * 8 + (l15 & 7)) * 128 + s * 32 + ((l15 >> 3) & 1) * 16));
                LDSM2(bf[nt][0], bf[nt][1], bbase + ro);
            }
            #pragma unroll
            for (int mt = 0; mt < 4; mt++)
                #pragma unroll
                for (int nt = 0; nt < 4; nt++)
                    mma16816(acc[mt][nt], af[mt], bf[nt]);
        }

        __syncthreads();
        if (st + 3 < 12) issue(st + 3);
        else CP_COMMIT();                      // empty group keeps wait_group(2) invariant
    }

    // ---- epilogue: scores + per-row argmin ----
    float rv[8]; int ri[8];
    #pragma unroll
    for (int mt = 0; mt < 4; mt++)
        #pragma unroll
        for (int h = 0; h < 2; h++) {
            int sl = mt * 2 + h;
            float bv = 3.4e38f; int bi = 0;
            #pragma unroll
            for (int nt = 0; nt < 4; nt++) {
                int col = wc * 32 + nt * 8 + 2 * (lane & 3);
                float v0 = cs[col]     - 2.0f * acc[mt][nt][h * 2 + 0];
                float v1 = cs[col + 1] - 2.0f * acc[mt][nt][h * 2 + 1];
                if (v0 < bv) { bv = v0; bi = col; }
                if (v1 < bv) { bv = v1; bi = col + 1; }
            }
            rv[sl] = bv; ri[sl] = bi;
        }
    #pragma unroll
    for (int o = 1; o <= 2; o <<= 1)
        #pragma unroll
        for (int sl = 0; sl < 8; sl++) {
            float v = __shfl_xor_sync(0xffffffffu, rv[sl], o);
            int   i = __shfl_xor_sync(0xffffffffu, ri[sl], o);
            if (v < rv[sl] || (v == rv[sl] && i < ri[sl])) { rv[sl] = v; ri[sl] = i; }
        }
    float* red_v = (float*)(smem + SM_RV);
    int*   red_i = (int*)(smem + SM_RI);
    if ((lane & 3) == 0) {
        #pragma unroll
        for (int mt = 0; mt < 4; mt++)
            #pragma unroll
            for (int h = 0; h < 2; h++) {
                int sl = mt * 2 + h;
                int rl = wr * 64 + mt * 16 + (lane >> 2) + 8 * h;
                red_v[wc * 128 + rl] = rv[sl];
                red_i[wc * 128 + rl] = ri[sl];
            }
    }
    __syncthreads();
    if (tid < 128) {
        float bv = red_v[tid]; int bi = red_i[tid];
        #pragma unroll
        for (int w = 1; w < 4; w++) {
            float v = red_v[w * 128 + tid]; int i = red_i[w * 128 + tid];
            if (v < bv || (v == bv && i < bi)) { bv = v; bi = i; }
        }
        g_minv[(size_t)(row0 + tid) * 32 + cg] = bv;
        g_mini[(size_t)(row0 + tid) * 32 + cg] = kc0 + bi;
    }
}

// ================= merge / epilogue kernels =================
__global__ void k_merge(float* __restrict__ out_idx) {
    int n = blockIdx.x * blockDim.x + threadIdx.x;
    if (n >= NROWS) return;
    float bv = g_minv[(size_t)n * 32]; int bi = g_mini[(size_t)n * 32];
    #pragma unroll
    for (int c = 1; c < 32; c++) {
        float v = g_minv[(size_t)n * 32 + c]; int ii = g_mini[(size_t)n * 32 + c];
        if (v < bv || (v == bv && ii < bi)) { bv = v; bi = ii; }
    }
    g_idx[n] = bi;
    out_idx[n] = (float)bi;
}

__global__ void k_scatter(const float* __restrict__ X, float* __restrict__ out_q) {
    int row = blockIdx.x * 8 + (threadIdx.x >> 5);
    int lane = threadIdx.x & 31;
    int k = g_idx[row];
    const float4* et = (const float4*)(g_ET + (size_t)k * D);
    const float4* xr = (const float4*)(X + (size_t)row * D);
    float4* qo = (float4*)(out_q + (size_t)row * D);
    float ls = 0.f;
    #pragma unroll
    for (int it = 0; it < 2; it++) {
        int v = it * 32 + lane;
        float4 q = et[v];
        float4 xv = xr[v];
        qo[v] = q;
        float dx = q.x - xv.x, dy = q.y - xv.y, dz = q.z - xv.z, dw = q.w - xv.w;
        ls += dx * dx + dy * dy + dz * dz + dw * dw;
        int d = v * 4;
        atomicAdd(&g_dw[(size_t)(d + 0) * K + k], xv.x);
        atomicAdd(&g_dw[(size_t)(d + 1) * K + k], xv.y);
        atomicAdd(&g_dw[(size_t)(d + 2) * K + k], xv.z);
        atomicAdd(&g_dw[(size_t)(d + 3) * K + k], xv.w);
    }
    #pragma unroll
    for (int o = 16; o; o >>= 1) ls += __shfl_down_sync(0xffffffffu, ls, o);
    if (lane == 0) { atomicAdd(&g_loss, ls); atomicAdd(&g_counts[k], 1); }
}

__global__ void k_stats(const float* __restrict__ ema_counter,
                        const float* __restrict__ ema_cluster,
                        float* __restrict__ out) {
    __shared__ float sh[64];
    __shared__ float sh_n;
    int tid = threadIdx.x;
    float counter = ema_counter[0] + 1.0f;
    float bias = 1.0f - powf(DECAY, counter);
    float cavg[4]; float npart = 0.f, epart = 0.f;
    #pragma unroll
    for (int j = 0; j < 4; j++) {
        int k = tid + j * 1024;
        float cnt = (float)g_counts[k];
        float ch = ema_cluster[k] * DECAY + cnt * ONE_MINUS_DECAY;
        float ca = ch / bias;
        cavg[j] = ca; npart += ca;
        float p = cnt * (1.0f / (float)NROWS);
        epart += p * logf(p + 1e-10f);
    }
    #pragma unroll
    for (int o = 16; o; o >>= 1) {
        npart += __shfl_down_sync(0xffffffffu, npart, o);
        epart += __shfl_down_sync(0xffffffffu, epart, o);
    }
    if ((tid & 31) == 0) { sh[tid >> 5] = npart; sh[32 + (tid >> 5)] = epart; }
    __syncthreads();
    if (tid < 32) {
        float a = sh[tid], b = sh[32 + tid];
        #pragma unroll
        for (int o = 16; o; o >>= 1) {
            a += __shfl_down_sync(0xffffffffu, a, o);
            b += __shfl_down_sync(0xffffffffu, b, o);
        }
        if (tid == 0) {
            sh_n = a;
            out[OFF_PERP] = expf(-b);
            float el = g_loss / (float)((size_t)NROWS * D);
            out[OFF_LOSS] = el + COMMIT * el;
            g_bias = bias;
        }
    }
    __syncthreads();
    float n = sh_n;
    #pragma unroll
    for (int j = 0; j < 4; j++) {
        int k = tid + j * 1024;
        g_cnorm[k] = (cavg[j] + EPSV) / (n + (float)K * EPSV) * n;
    }
}

__global__ void k_newemb(const float* __restrict__ ema_dw, float* __restrict__ out_ne) {
    int i = blockIdx.x * 256 + threadIdx.x;
    int k = i & (K - 1);
    float dwh = ema_dw[i] * DECAY + g_dw[i] * ONE_MINUS_DECAY;
    out_ne[i] = (dwh / g_bias) / g_cnorm[k];
}

// ================= launch =================
extern "C" void kernel_launch(void* const* d_in, const int* in_sizes, int n_in,
                              void* d_out, int out_size) {
    const float* x   = (const float*)d_in[0];
    const float* emb = (const float*)d_in[1];
    const float* ctr = (const float*)d_in[2];
    const float* ecl = (const float*)d_in[3];
    const float* edw = (const float*)d_in[4];
    float* out = (float*)d_out;

    cudaFuncSetAttribute(k_argmin, cudaFuncAttributeMaxDynamicSharedMemorySize, SMEM_SZ);

    k_zero<<<1024, 256>>>();
    k_ce<<<K / 256, 256>>>(emb);
    k_transpose<<<dim3(K / 32, D / 32), dim3(32, 8)>>>(emb);
    k_esplit<<<(K * D / 4) / 256, 256>>>();
    k_xsplit<<<(NROWS * D / 4) / 256, 256>>>(x);
    k_argmin<<<8192, 256, SMEM_SZ>>>();
    k_merge<<<NROWS / 256, 256>>>(out + OFF_IDX);
    k_scatter<<<NROWS / 8, 256>>>(x, out + OFF_Q);
    k_stats<<<1, 1024>>>(ctr, ecl, out);
    k_newemb<<<(D * K) / 256, 256>>>(edw, out + OFF_NE);
}

// round 5
// speedup vs baseline: 4.5264x; 1.5722x over previous
#include <cuda_runtime.h>
#include <cuda_fp16.h>
#include <cstdint>

#define NROWS 32768
#define D 256
#define K 4096
#define DECAY 0.99f
#define ONE_MINUS_DECAY 0.01f
#define EPSV 1e-5f
#define COMMIT 0.25f

static const size_t OFF_Q    = 0;
static const size_t OFF_LOSS = 8388608;
static const size_t OFF_PERP = 8388609;
static const size_t OFF_IDX  = 8388610;
static const size_t OFF_NE   = 8421378;

// -------- device scratch --------
__device__ float g_ce[K];
__device__ float g_ET[(size_t)K * D];
__device__ __align__(16) __half g_xh[(size_t)NROWS * D];
__device__ __align__(16) __half g_eh[(size_t)K * D];
__device__ float g_dw[(size_t)D * K];
__device__ int   g_counts[K];
__device__ float g_t2v[(size_t)64 * NROWS];   // [plane=cg*2+j][row]
__device__ int   g_t2i[(size_t)64 * NROWS];
__device__ float g_loss;
__device__ float g_bias;
__device__ float g_cnorm[K];

// ================= PTX helpers =================
__device__ __forceinline__ uint32_t smem_to_u32(const void* p) {
    uint32_t a;
    asm("{ .reg .u64 t; cvta.to.shared.u64 t, %1; cvt.u32.u64 %0, t; }" : "=r"(a) : "l"(p));
    return a;
}
__device__ __forceinline__ void cp16(uint32_t saddr, const void* g) {
    asm volatile("cp.async.cg.shared.global [%0], [%1], 16;" :: "r"(saddr), "l"(g));
}
#define CP_COMMIT() asm volatile("cp.async.commit_group;" ::: "memory")
#define CP_WAIT2()  asm volatile("cp.async.wait_group 2;" ::: "memory")

#define LDSM4(r0, r1, r2, r3, a) \
    asm volatile("ldmatrix.sync.aligned.m8n8.x4.shared.b16 {%0,%1,%2,%3}, [%4];" \
        : "=r"(r0), "=r"(r1), "=r"(r2), "=r"(r3) : "r"(a))
#define LDSM2(r0, r1, a) \
    asm volatile("ldmatrix.sync.aligned.m8n8.x2.shared.b16 {%0,%1}, [%2];" \
        : "=r"(r0), "=r"(r1) : "r"(a))

__device__ __forceinline__ void mma16816(float* c, const uint32_t* a, const uint32_t* b) {
    asm volatile("mma.sync.aligned.m16n8k16.row.col.f32.f16.f16.f32 "
        "{%0,%1,%2,%3}, {%4,%5,%6,%7}, {%8,%9}, {%0,%1,%2,%3};"
        : "+f"(c[0]), "+f"(c[1]), "+f"(c[2]), "+f"(c[3])
        : "r"(a[0]), "r"(a[1]), "r"(a[2]), "r"(a[3]), "r"(b[0]), "r"(b[1]));
}

__device__ __forceinline__ uint32_t sw128(uint32_t b) { return b ^ ((b >> 3) & 0x70); }

// ================= small kernels =================
__global__ void k_zero() {
    int i = blockIdx.x * blockDim.x + threadIdx.x, st = gridDim.x * blockDim.x;
    for (int j = i; j < D * K; j += st) g_dw[j] = 0.f;
    for (int j = i; j < K; j += st) g_counts[j] = 0;
    if (i == 0) g_loss = 0.f;
}

__global__ void k_ce(const float* __restrict__ E) {
    int k = blockIdx.x * 256 + threadIdx.x;
    float s = 0.f;
    #pragma unroll 8
    for (int d = 0; d < D; d++) { float v = E[(size_t)d * K + k]; s = fmaf(v, v, s); }
    g_ce[k] = s;
}

__global__ void k_transpose(const float* __restrict__ E) {
    __shared__ float t[32][33];
    int kb = blockIdx.x * 32, db = blockIdx.y * 32;
    int x = threadIdx.x, y0 = threadIdx.y;
    #pragma unroll
    for (int j = 0; j < 32; j += 8) t[y0 + j][x] = E[(size_t)(db + y0 + j) * K + kb + x];
    __syncthreads();
    #pragma unroll
    for (int j = 0; j < 32; j += 8) g_ET[(size_t)(kb + y0 + j) * D + db + x] = t[x][y0 + j];
}

// convert 8 floats -> 8 halfs per thread
__global__ void k_xh(const float* __restrict__ X) {
    size_t i = (size_t)blockIdx.x * 256 + threadIdx.x;
    float4 a = *(const float4*)(X + i * 8);
    float4 b = *(const float4*)(X + i * 8 + 4);
    __half h[8] = { __float2half_rn(a.x), __float2half_rn(a.y), __float2half_rn(a.z), __float2half_rn(a.w),
                    __float2half_rn(b.x), __float2half_rn(b.y), __float2half_rn(b.z), __float2half_rn(b.w) };
    *(uint4*)(g_xh + i * 8) = *(uint4*)h;
}

__global__ void k_eh() {
    size_t i = (size_t)blockIdx.x * 256 + threadIdx.x;
    float4 a = *(const float4*)(g_ET + i * 8);
    float4 b = *(const float4*)(g_ET + i * 8 + 4);
    __half h[8] = { __float2half_rn(a.x), __float2half_rn(a.y), __float2half_rn(a.z), __float2half_rn(a.w),
                    __float2half_rn(b.x), __float2half_rn(b.y), __float2half_rn(b.z), __float2half_rn(b.w) };
    *(uint4*)(g_eh + i * 8) = *(uint4*)h;
}

// ================= approx argmin GEMM (HMMA, K=256, top-2 per tile) =================
#define ST_SZ   32768
#define SM_CS   98304
#define SMEM_SZ 98816

__global__ void __launch_bounds__(256, 2)
k_argmin() {
    extern __shared__ char smem[];
    const int tid = threadIdx.x;
    const int wid = tid >> 5, lane = tid & 31;
    const int rt = blockIdx.x >> 5, cg = blockIdx.x & 31;
    const int row0 = rt * 128, kc0 = cg * 128;
    const int wr = wid >> 2, wc = wid & 3;
    const uint32_t sb = smem_to_u32(smem);

    float* cs = (float*)(smem + SM_CS);
    if (tid < 128) cs[tid] = g_ce[kc0 + tid];

    const __half* Ag = g_xh + (size_t)row0 * D;
    const __half* Bg = g_eh + (size_t)kc0 * D;

    float acc[4][4][4];
    #pragma unroll
    for (int mt = 0; mt < 4; mt++)
        #pragma unroll
        for (int nt = 0; nt < 4; nt++)
            #pragma unroll
            for (int j = 0; j < 4; j++) acc[mt][nt][j] = 0.f;

    auto issue = [&](int st) {
        int buf = st - (st / 3) * 3;
        uint32_t abase = sb + (uint32_t)buf * ST_SZ;
        uint32_t bbase = abase + 16384;
        int k0 = st * 64;
        #pragma unroll
        for (int j = 0; j < 4; j++) {
            int chunk = tid + j * 256;
            int r = chunk >> 3, cc = chunk & 7;
            uint32_t so = sw128((uint32_t)(r * 128 + cc * 16));
            cp16(abase + so, Ag + (size_t)r * D + k0 + cc * 8);
            cp16(bbase + so, Bg + (size_t)r * D + k0 + cc * 8);
        }
        CP_COMMIT();
    };

    issue(0); issue(1); issue(2);

    const int l15 = lane & 15;

    #pragma unroll 1
    for (int st = 0; st < 4; st++) {
        CP_WAIT2();
        __syncthreads();
        int buf = st - (st / 3) * 3;
        uint32_t abase = sb + (uint32_t)buf * ST_SZ;
        uint32_t bbase = abase + 16384;

        #pragma unroll
        for (int s = 0; s < 4; s++) {
            uint32_t af[4][4], bf[4][2];
            #pragma unroll
            for (int mt = 0; mt < 4; mt++) {
                uint32_t ro = sw128((uint32_t)((wr * 64 + mt * 16 + l15) * 128 + s * 32 + (lane >> 4) * 16));
                LDSM4(af[mt][0], af[mt][1], af[mt][2], af[mt][3], abase + ro);
            }
            #pragma unroll
            for (int nt = 0; nt < 4; nt++) {
                uint32_t ro = sw128((uint32_t)((wc * 32 + nt * 8 + (l15 & 7)) * 128 + s * 32 + ((l15 >> 3) & 1) * 16));
                LDSM2(bf[nt][0], bf[nt][1], bbase + ro);
            }
            #pragma unroll
            for (int mt = 0; mt < 4; mt++)
                #pragma unroll
                for (int nt = 0; nt < 4; nt++)
                    mma16816(acc[mt][nt], af[mt], bf[nt]);
        }

        __syncthreads();
        if (st + 3 < 4) issue(st + 3);
        else CP_COMMIT();
    }

    // ---- scores -> smem (stride 129 to kill bank conflicts) ----
    float* sc = (float*)smem;
    #pragma unroll
    for (int mt = 0; mt < 4; mt++)
        #pragma unroll
        for (int h = 0; h < 2; h++) {
            int row = wr * 64 + mt * 16 + (lane >> 2) + 8 * h;
            #pragma unroll
            for (int nt = 0; nt < 4; nt++) {
                int col = wc * 32 + nt * 8 + 2 * (lane & 3);
                sc[row * 129 + col]     = cs[col]     - 2.0f * acc[mt][nt][h * 2 + 0];
                sc[row * 129 + col + 1] = cs[col + 1] - 2.0f * acc[mt][nt][h * 2 + 1];
            }
        }
    __syncthreads();

    // ---- per-row top-2 scan (tie -> smaller index via strict <) ----
    if (tid < 128) {
        float v1 = 3.4e38f, v2 = 3.4e38f; int i1 = 0, i2 = 0;
        #pragma unroll 8
        for (int c = 0; c < 128; c++) {
            float v = sc[tid * 129 + c];
            if (v < v1) { v2 = v1; i2 = i1; v1 = v; i1 = c; }
            else if (v < v2) { v2 = v; i2 = c; }
        }
        size_t n = (size_t)(row0 + tid);
        g_t2v[(size_t)(cg * 2 + 0) * NROWS + n] = v1;
        g_t2i[(size_t)(cg * 2 + 0) * NROWS + n] = kc0 + i1;
        g_t2v[(size_t)(cg * 2 + 1) * NROWS + n] = v2;
        g_t2i[(size_t)(cg * 2 + 1) * NROWS + n] = kc0 + i2;
    }
}

// ================= select (top-4 merge + exact rescore) + scatter =================
__device__ __forceinline__ bool lt2(float v, int i, float u, int j) {
    return v < u || (v == u && i < j);
}

__global__ void __launch_bounds__(256)
k_select(const float* __restrict__ X, float* __restrict__ out_q, float* __restrict__ out_idx) {
    const int wid = threadIdx.x >> 5, lane = threadIdx.x & 31;
    const size_t n = (size_t)blockIdx.x * 8 + wid;

    float t4v[4]; int t4i[4];
    t4v[0] = g_t2v[(size_t)(lane * 2) * NROWS + n];
    t4i[0] = g_t2i[(size_t)(lane * 2) * NROWS + n];
    t4v[1] = g_t2v[(size_t)(lane * 2 + 1) * NROWS + n];
    t4i[1] = g_t2i[(size_t)(lane * 2 + 1) * NROWS + n];
    t4v[2] = t4v[3] = 3.4e38f; t4i[2] = t4i[3] = 0x7fffffff;

    #pragma unroll
    for (int o = 1; o < 32; o <<= 1) {
        float rv[4]; int ri[4];
        #pragma unroll
        for (int s = 0; s < 4; s++) {
            rv[s] = __shfl_xor_sync(0xffffffffu, t4v[s], o);
            ri[s] = __shfl_xor_sync(0xffffffffu, t4i[s], o);
        }
        #pragma unroll
        for (int s = 0; s < 4; s++) {
            float v = rv[s]; int i = ri[s];
            if (lt2(v, i, t4v[3], t4i[3])) {
                if (lt2(v, i, t4v[0], t4i[0])) {
                    t4v[3]=t4v[2]; t4i[3]=t4i[2]; t4v[2]=t4v[1]; t4i[2]=t4i[1];
                    t4v[1]=t4v[0]; t4i[1]=t4i[0]; t4v[0]=v; t4i[0]=i;
                } else if (lt2(v, i, t4v[1], t4i[1])) {
                    t4v[3]=t4v[2]; t4i[3]=t4i[2]; t4v[2]=t4v[1]; t4i[2]=t4i[1];
                    t4v[1]=v; t4i[1]=i;
                } else if (lt2(v, i, t4v[2], t4i[2])) {
                    t4v[3]=t4v[2]; t4i[3]=t4i[2]; t4v[2]=v; t4i[2]=i;
                } else {
                    t4v[3]=v; t4i[3]=i;
                }
            }
        }
    }

    // exact fp32 rescore of 4 candidates
    const float4* xr = (const float4*)(X + n * D);
    float4 xa = xr[lane * 2], xb = xr[lane * 2 + 1];
    float bs = 3.4e38f; int bk = 0x7fffffff;
    #pragma unroll 1
    for (int c = 0; c < 4; c++) {
        int k = t4i[c];
        const float4* er = (const float4*)(g_ET + (size_t)k * D);
        float4 ea = er[lane * 2], eb = er[lane * 2 + 1];
        float d = xa.x*ea.x + xa.y*ea.y + xa.z*ea.z + xa.w*ea.w
                + xb.x*eb.x + xb.y*eb.y + xb.z*eb.z + xb.w*eb.w;
        float q = ea.x*ea.x + ea.y*ea.y + ea.z*ea.z + ea.w*ea.w
                + eb.x*eb.x + eb.y*eb.y + eb.z*eb.z + eb.w*eb.w;
        #pragma unroll
        for (int o = 16; o; o >>= 1) {
            d += __shfl_xor_sync(0xffffffffu, d, o);
            q += __shfl_xor_sync(0xffffffffu, q, o);
        }
        float s = q - 2.0f * d;
        if (s < bs || (s == bs && k < bk)) { bs = s; bk = k; }
    }

    // scatter: quantized, loss, dw atomics, counts
    const float4* er = (const float4*)(g_ET + (size_t)bk * D);
    float4 ea = er[lane * 2], eb = er[lane * 2 + 1];
    float4* qo = (float4*)(out_q + n * D);
    qo[lane * 2] = ea; qo[lane * 2 + 1] = eb;
    float dx0 = ea.x - xa.x, dx1 = ea.y - xa.y, dx2 = ea.z - xa.z, dx3 = ea.w - xa.w;
    float dx4 = eb.x - xb.x, dx5 = eb.y - xb.y, dx6 = eb.z - xb.z, dx7 = eb.w - xb.w;
    float ls = dx0*dx0 + dx1*dx1 + dx2*dx2 + dx3*dx3 + dx4*dx4 + dx5*dx5 + dx6*dx6 + dx7*dx7;

    int d0 = lane * 8;
    atomicAdd(&g_dw[(size_t)(d0 + 0) * K + bk], xa.x);
    atomicAdd(&g_dw[(size_t)(d0 + 1) * K + bk], xa.y);
    atomicAdd(&g_dw[(size_t)(d0 + 2) * K + bk], xa.z);
    atomicAdd(&g_dw[(size_t)(d0 + 3) * K + bk], xa.w);
    atomicAdd(&g_dw[(size_t)(d0 + 4) * K + bk], xb.x);
    atomicAdd(&g_dw[(size_t)(d0 + 5) * K + bk], xb.y);
    atomicAdd(&g_dw[(size_t)(d0 + 6) * K + bk], xb.z);
    atomicAdd(&g_dw[(size_t)(d0 + 7) * K + bk], xb.w);

    #pragma unroll
    for (int o = 16; o; o >>= 1) ls += __shfl_down_sync(0xffffffffu, ls, o);
    if (lane == 0) {
        atomicAdd(&g_loss, ls);
        atomicAdd(&g_counts[bk], 1);
        out_idx[n] = (float)bk;
    }
}

// ================= stats / new embeddings =================
__global__ void k_stats(const float* __restrict__ ema_counter,
                        const float* __restrict__ ema_cluster,
                        float* __restrict__ out) {
    __shared__ float sh[64];
    __shared__ float sh_n;
    int tid = threadIdx.x;
    float counter = ema_counter[0] + 1.0f;
    float bias = 1.0f - powf(DECAY, counter);
    float cavg[4]; float npart = 0.f, epart = 0.f;
    #pragma unroll
    for (int j = 0; j < 4; j++) {
        int k = tid + j * 1024;
        float cnt = (float)g_counts[k];
        float ch = ema_cluster[k] * DECAY + cnt * ONE_MINUS_DECAY;
        float ca = ch / bias;
        cavg[j] = ca; npart += ca;
        float p = cnt * (1.0f / (float)NROWS);
        epart += p * logf(p + 1e-10f);
    }
    #pragma unroll
    for (int o = 16; o; o >>= 1) {
        npart += __shfl_down_sync(0xffffffffu, npart, o);
        epart += __shfl_down_sync(0xffffffffu, epart, o);
    }
    if ((tid & 31) == 0) { sh[tid >> 5] = npart; sh[32 + (tid >> 5)] = epart; }
    __syncthreads();
    if (tid < 32) {
        float a = sh[tid], b = sh[32 + tid];
        #pragma unroll
        for (int o = 16; o; o >>= 1) {
            a += __shfl_down_sync(0xffffffffu, a, o);
            b += __shfl_down_sync(0xffffffffu, b, o);
        }
        if (tid == 0) {
            sh_n = a;
            out[OFF_PERP] = expf(-b);
            float el = g_loss / (float)((size_t)NROWS * D);
            out[OFF_LOSS] = el + COMMIT * el;
            g_bias = bias;
        }
    }
    __syncthreads();
    float n = sh_n;
    #pragma unroll
    for (int j = 0; j < 4; j++) {
        int k = tid + j * 1024;
        g_cnorm[k] = (cavg[j] + EPSV) / (n + (float)K * EPSV) * n;
    }
}

__global__ void k_newemb(const float* __restrict__ ema_dw, float* __restrict__ out_ne) {
    int i = blockIdx.x * 256 + threadIdx.x;
    int k = i & (K - 1);
    float dwh = ema_dw[i] * DECAY + g_dw[i] * ONE_MINUS_DECAY;
    out_ne[i] = (dwh / g_bias) / g_cnorm[k];
}

// ================= launch =================
extern "C" void kernel_launch(void* const* d_in, const int* in_sizes, int n_in,
                              void* d_out, int out_size) {
    const float* x   = (const float*)d_in[0];
    const float* emb = (const float*)d_in[1];
    const float* ctr = (const float*)d_in[2];
    const float* ecl = (const float*)d_in[3];
    const float* edw = (const float*)d_in[4];
    float* out = (float*)d_out;

    cudaFuncSetAttribute(k_argmin, cudaFuncAttributeMaxDynamicSharedMemorySize, SMEM_SZ);

    k_zero<<<1024, 256>>>();
    k_ce<<<K / 256, 256>>>(emb);
    k_transpose<<<dim3(K / 32, D / 32), dim3(32, 8)>>>(emb);
    k_eh<<<(K * D / 8) / 256, 256>>>();
    k_xh<<<((size_t)NROWS * D / 8) / 256, 256>>>(x);
    k_argmin<<<8192, 256, SMEM_SZ>>>();
    k_select<<<NROWS / 8, 256>>>(x, out + OFF_Q, out + OFF_IDX);
    k_stats<<<1, 1024>>>(ctr, ecl, out);
    k_newemb<<<(D * K) / 256, 256>>>(edw, out + OFF_NE);
}